// round 12
// baseline (speedup 1.0000x reference)
#include <cuda_runtime.h>
#include <cuda_fp16.h>
#include <cuda_bf16.h>

// out[m,n] = tanh( sum_h w2[h] * tanh( w1[h][0]*A[m,n] + w1[h][1]*pre[n]
//                                    + w1[h][2]*post[m] + b1[h] ) + b2 )
// M = N = 4096, Nh = 8.
//
// Latency-bound (R11 finding: MUFU cut 9->5 ops/elem moved runtime only 2%;
// no pipe saturated). This version: one block per row (256 thr x 16 elem =
// 4096 = N), A-loads front-batched for MLP=4, weight preamble amortized over
// 16 elements. Inner tanh kept pairwise f16x2 (rel_err-proven 2.5e-4).

#define NH 8

__device__ __forceinline__ float htanh(float x) {
    float y;
    asm("tanh.approx.f32 %0, %1;" : "=f"(y) : "f"(x));
    return y;
}

__device__ __forceinline__ __half2 htanh2(__half2 x) {
    __half2 y;
    asm("tanh.approx.f16x2 %0, %1;"
        : "=r"(*(unsigned int*)&y) : "r"(*(const unsigned int*)&x));
    return y;
}

__global__ __launch_bounds__(256) void synapse_kernel(
    const float* __restrict__ A,
    const float* __restrict__ pre,
    const float* __restrict__ post,
    const float* __restrict__ w1,   // [NH, 3]
    const float* __restrict__ b1,   // [NH]
    const float* __restrict__ w2,   // [1, NH]
    const float* __restrict__ b2,   // [1]
    float* __restrict__ out,
    int M, int N)
{
    const int row = blockIdx.x;           // one block per row; N == 16*blockDim.x
    const int tid = threadIdx.x;
    const int n4  = N >> 2;               // float4s per row (1024)

    const float4* A4 = (const float4*)A;
    const float4* P4 = (const float4*)pre;
    float4*       O4 = (float4*)out;

    // This thread's 4 float4 chunks (16 consecutive elements of the row).
    const long long rowBase = (long long)row * n4;
    const int c0 = tid * 4;

    // Front-batch the DRAM-latency loads (A): MLP = 4.
    float4 a0 = __ldg(&A4[rowBase + c0 + 0]);
    float4 a1 = __ldg(&A4[rowBase + c0 + 1]);
    float4 a2 = __ldg(&A4[rowBase + c0 + 2]);
    float4 a3 = __ldg(&A4[rowBase + c0 + 3]);

    // Tiny weight tensors (L1/L2 cached; amortized over 16 elements).
    float w10[NH], w11[NH], t[NH], v2[NH];
    const float pm = __ldg(&post[row]);
#pragma unroll
    for (int h = 0; h < NH; ++h) {
        w10[h] = __ldg(&w1[h * 3 + 0]);
        w11[h] = __ldg(&w1[h * 3 + 1]);
        float w12 = __ldg(&w1[h * 3 + 2]);
        t[h] = fmaf(w12, pm, __ldg(&b1[h]));   // per-row hoisted term
        v2[h] = __ldg(&w2[h]);
    }
    const float bb2 = __ldg(&b2[0]);

    float4 areg[4] = {a0, a1, a2, a3};

#pragma unroll
    for (int c = 0; c < 4; ++c) {
        float4 a = areg[c];
        float4 p = __ldg(&P4[c0 + c]);        // L1/L2 resident

        float av[4] = {a.x, a.y, a.z, a.w};
        float pv[4] = {p.x, p.y, p.z, p.w};
        float ov[4];

        // 2 pairs; each pair shares one f16x2 tanh per hidden unit.
#pragma unroll
        for (int q = 0; q < 2; ++q) {
            const int e0 = 2 * q, e1 = 2 * q + 1;
            float acc0 = bb2, acc1 = bb2;
#pragma unroll
            for (int h = 0; h < NH; ++h) {
                float arg0 = fmaf(w10[h], av[e0], fmaf(w11[h], pv[e0], t[h]));
                float arg1 = fmaf(w10[h], av[e1], fmaf(w11[h], pv[e1], t[h]));
                __half2 ar = __floats2half2_rn(arg0, arg1);
                __half2 th = htanh2(ar);
                float2 tf = __half22float2(th);
                acc0 = fmaf(v2[h], tf.x, acc0);
                acc1 = fmaf(v2[h], tf.y, acc1);
            }
            ov[e0] = htanh(acc0);
            ov[e1] = htanh(acc1);
        }

        float4 o;
        o.x = ov[0]; o.y = ov[1]; o.z = ov[2]; o.w = ov[3];
        O4[rowBase + c0 + c] = o;
    }
}

extern "C" void kernel_launch(void* const* d_in, const int* in_sizes, int n_in,
                              void* d_out, int out_size) {
    const float* A    = (const float*)d_in[0];
    const float* pre  = (const float*)d_in[1];
    const float* post = (const float*)d_in[2];
    const float* w1   = (const float*)d_in[3];
    const float* b1   = (const float*)d_in[4];
    const float* w2   = (const float*)d_in[5];
    const float* b2   = (const float*)d_in[6];
    float* out = (float*)d_out;

    int N = in_sizes[1];          // len(pre) = 4096
    int M = in_sizes[2];          // len(post) = 4096

    // One block per row: 256 threads x 16 elements = 4096 = N.
    int block = 256;
    int grid = M;

    synapse_kernel<<<grid, block>>>(A, pre, post, w1, b1, w2, b2, out, M, N);
}

// round 13
// speedup vs baseline: 1.4885x; 1.4885x over previous
#include <cuda_runtime.h>
#include <cuda_fp16.h>
#include <cuda_bf16.h>

// out[m,n] = tanh( sum_h w2[h] * tanh( w1[h][0]*A[m,n] + w1[h][1]*pre[n]
//                                    + w1[h][2]*post[m] + b1[h] ) + b2 )
// M = N = 4096, Nh = 8.
//
// R12 finding: runtime tracks L1tex wavefronts. Consecutive-per-thread
// float4s made each warp load touch 16 lines (4x amplification) -> 62us.
// This version: block-per-row, WARP-STRIDED float4 accesses (chunk c at
// tid + c*256) -> every load/store is fully coalesced (4 lines/warp instr,
// the minimum). A-loads front-batched (MLP=4). Inner tanh pairwise f16x2.

#define NH 8

__device__ __forceinline__ float htanh(float x) {
    float y;
    asm("tanh.approx.f32 %0, %1;" : "=f"(y) : "f"(x));
    return y;
}

__device__ __forceinline__ __half2 htanh2(__half2 x) {
    __half2 y;
    asm("tanh.approx.f16x2 %0, %1;"
        : "=r"(*(unsigned int*)&y) : "r"(*(const unsigned int*)&x));
    return y;
}

__global__ __launch_bounds__(256) void synapse_kernel(
    const float* __restrict__ A,
    const float* __restrict__ pre,
    const float* __restrict__ post,
    const float* __restrict__ w1,   // [NH, 3]
    const float* __restrict__ b1,   // [NH]
    const float* __restrict__ w2,   // [1, NH]
    const float* __restrict__ b2,   // [1]
    float* __restrict__ out,
    int M, int N)
{
    const int row = blockIdx.x;           // one block per row; N == 16*blockDim.x
    const int tid = threadIdx.x;
    const int n4  = N >> 2;               // float4s per row (1024)
    const int bdim = blockDim.x;          // 256

    const float4* A4 = (const float4*)A;
    const float4* P4 = (const float4*)pre;
    float4*       O4 = (float4*)out;

    const long long rowBase = (long long)row * n4;

    // Warp-strided chunks: chunk c is at float4 index tid + c*256.
    // Every warp instruction covers 512 contiguous bytes (fully coalesced).
    // Front-batch the DRAM-latency A loads: MLP = 4.
    float4 a0 = __ldg(&A4[rowBase + tid + 0 * bdim]);
    float4 a1 = __ldg(&A4[rowBase + tid + 1 * bdim]);
    float4 a2 = __ldg(&A4[rowBase + tid + 2 * bdim]);
    float4 a3 = __ldg(&A4[rowBase + tid + 3 * bdim]);

    // Tiny weight tensors (L1/L2 cached; amortized over 16 elements).
    float w10[NH], w11[NH], t[NH], v2[NH];
    const float pm = __ldg(&post[row]);
#pragma unroll
    for (int h = 0; h < NH; ++h) {
        w10[h] = __ldg(&w1[h * 3 + 0]);
        w11[h] = __ldg(&w1[h * 3 + 1]);
        float w12 = __ldg(&w1[h * 3 + 2]);
        t[h] = fmaf(w12, pm, __ldg(&b1[h]));   // per-row hoisted term
        v2[h] = __ldg(&w2[h]);
    }
    const float bb2 = __ldg(&b2[0]);

    float4 areg[4] = {a0, a1, a2, a3};

#pragma unroll
    for (int c = 0; c < 4; ++c) {
        const int col4 = tid + c * bdim;      // coalesced position
        float4 a = areg[c];
        float4 p = __ldg(&P4[col4]);          // L1/L2 resident, coalesced

        float av[4] = {a.x, a.y, a.z, a.w};
        float pv[4] = {p.x, p.y, p.z, p.w};
        float ov[4];

        // 2 pairs; each pair shares one f16x2 tanh per hidden unit.
#pragma unroll
        for (int q = 0; q < 2; ++q) {
            const int e0 = 2 * q, e1 = 2 * q + 1;
            float acc0 = bb2, acc1 = bb2;
#pragma unroll
            for (int h = 0; h < NH; ++h) {
                float arg0 = fmaf(w10[h], av[e0], fmaf(w11[h], pv[e0], t[h]));
                float arg1 = fmaf(w10[h], av[e1], fmaf(w11[h], pv[e1], t[h]));
                __half2 ar = __floats2half2_rn(arg0, arg1);
                __half2 th = htanh2(ar);
                float2 tf = __half22float2(th);
                acc0 = fmaf(v2[h], tf.x, acc0);
                acc1 = fmaf(v2[h], tf.y, acc1);
            }
            ov[e0] = htanh(acc0);
            ov[e1] = htanh(acc1);
        }

        float4 o;
        o.x = ov[0]; o.y = ov[1]; o.z = ov[2]; o.w = ov[3];
        O4[rowBase + col4] = o;               // coalesced store
    }
}

extern "C" void kernel_launch(void* const* d_in, const int* in_sizes, int n_in,
                              void* d_out, int out_size) {
    const float* A    = (const float*)d_in[0];
    const float* pre  = (const float*)d_in[1];
    const float* post = (const float*)d_in[2];
    const float* w1   = (const float*)d_in[3];
    const float* b1   = (const float*)d_in[4];
    const float* w2   = (const float*)d_in[5];
    const float* b2   = (const float*)d_in[6];
    float* out = (float*)d_out;

    int N = in_sizes[1];          // len(pre) = 4096
    int M = in_sizes[2];          // len(post) = 4096

    // One block per row: 256 threads x 16 elements = 4096 = N.
    int block = 256;
    int grid = M;

    synapse_kernel<<<grid, block>>>(A, pre, post, w1, b1, w2, b2, out, M, N);
}